// round 16
// baseline (speedup 1.0000x reference)
#include <cuda_runtime.h>

// x: (N=8, M=32, C=128, H=32, W=32) fp32.  D = H*W = 1024.
// 4096 independent classical Gram-Schmidt problems (one per (m,c)),
// each over NV=8 vectors of length 1024.
//
// R13 structure + smem-crossbar relief: Gram partials are pre-reduced TWO
// butterfly rounds in phase A, with the SHFLs interleaved 6-wide (groups of
// 6 entries) so the 26-cyc SHFL latencies pipeline.  Partial buffer shrinks
// 36KB -> 9KB; smem traffic per CTA drops 72KB -> 18KB, cutting the shared
// crossbar occupancy that was ~25% of the wave.
#define NV 8
#define DLEN 1024
#define NPROB 4096
#define NSTRIDE_F4 (NPROB * DLEN / 4)   // 1048576 float4 between n-slices
#define NG 36                           // lower-triangular entries

__device__ __forceinline__ float dot4(float4 a, float4 b) {
    return a.x * b.x + a.y * b.y + a.z * b.z + a.w * b.w;
}

__global__ void __launch_bounds__(256, 4)
gram_schmidt_kernel(const float* __restrict__ x, float* __restrict__ out) {
    const int p    = blockIdx.x;
    const int tid  = threadIdx.x;
    const int lane = tid & 31;
    const int warp = tid >> 5;

    const float4* __restrict__ xin =
        reinterpret_cast<const float4*>(x) + (size_t)p * (DLEN / 4) + tid;
    float4* __restrict__ xout =
        reinterpret_cast<float4*>(out) + (size_t)p * (DLEN / 4) + tid;

    __shared__ float part[NG][64];   // 9KB: 2-round pre-reduced partials
    __shared__ float Gf[NG];         // reduced Gram (packed lower tri)
    __shared__ float Tm[NG];         // GS transform matrix (packed lower tri)

    // ---- A: load all 8 vectors (batched LDG.128) ----
    float4 v[NV];
    #pragma unroll
    for (int n = 0; n < NV; n++) v[n] = xin[(size_t)n * NSTRIDE_F4];

    // Gram partials in groups of 6: dots, then 2 butterfly rounds with the
    // 6 chains interleaved, then predicated STS from lanes 0-7.
    {
        // flat (i,j) pairs of the packed lower triangle, in order
        #pragma unroll
        for (int g = 0; g < 6; g++) {
            float s[6];
            #pragma unroll
            for (int u = 0; u < 6; u++) {
                const int t = g * 6 + u;
                // invert t -> (i,j): i = floor((sqrt(8t+1)-1)/2), j = t - i(i+1)/2
                // done at compile time via constexpr-style unrolled search
                int i = 0;
                #pragma unroll
                for (int ii = 0; ii < NV; ii++)
                    if (t >= ii * (ii + 1) / 2) i = ii;
                const int j = t - i * (i + 1) / 2;
                s[u] = dot4(v[i], v[j]);
            }
            #pragma unroll
            for (int u = 0; u < 6; u++)
                s[u] += __shfl_xor_sync(0xffffffffu, s[u], 16);
            #pragma unroll
            for (int u = 0; u < 6; u++)
                s[u] += __shfl_xor_sync(0xffffffffu, s[u], 8);
            if (lane < 8) {
                #pragma unroll
                for (int u = 0; u < 6; u++)
                    part[g * 6 + u][warp * 8 + lane] = s[u];
            }
        }
    }
    __syncthreads();

    // ---- B: cooperative reduction, warp w owns entries w, w+8, ...; ----
    // 5 interleaved chains (R13 pattern), rows are 64 floats -> LDS.64.
    {
        float s[5];
        #pragma unroll
        for (int u = 0; u < 5; u++) {
            const int t = warp + u * 8;
            if (t < NG) {
                const float2* row = reinterpret_cast<const float2*>(part[t]);
                float2 a = row[lane];
                s[u] = a.x + a.y;
            } else {
                s[u] = 0.0f;
            }
        }
        #pragma unroll
        for (int m = 16; m >= 1; m >>= 1) {
            #pragma unroll
            for (int u = 0; u < 5; u++)
                s[u] += __shfl_xor_sync(0xffffffffu, s[u], m);
        }
        if (lane == 0) {
            #pragma unroll
            for (int u = 0; u < 5; u++) {
                const int t = warp + u * 8;
                if (t < NG) Gf[t] = s[u];
            }
        }
    }
    __syncthreads();

    // ---- C: warp 0 computes the triangular recursion (replicated lanes) ----
    if (warp == 0) {
        float G[NG];
        #pragma unroll
        for (int t = 0; t < NG; t++) G[t] = Gf[t];  // broadcast LDS

        float T[NG];
        {
            float inv = (G[0] > 0.0f) ? rsqrtf(G[0]) : 0.0f;
            T[0] = inv;
        }
        #pragma unroll
        for (int i = 1; i < NV; i++) {
            float c[NV];
            #pragma unroll
            for (int j = 0; j < i; j++) {
                float s = 0.0f;
                #pragma unroll
                for (int k = 0; k <= j; k++)
                    s += T[j * (j + 1) / 2 + k] * G[i * (i + 1) / 2 + k];
                c[j] = s;
            }
            float n2 = G[i * (i + 1) / 2 + i];
            #pragma unroll
            for (int j = 0; j < i; j++) n2 -= c[j] * c[j];
            float inv = (n2 > 0.0f) ? rsqrtf(n2) : 0.0f;

            #pragma unroll
            for (int k = 0; k < i; k++) {
                float s = 0.0f;
                #pragma unroll
                for (int j = k; j < i; j++)
                    s -= c[j] * T[j * (j + 1) / 2 + k];
                T[i * (i + 1) / 2 + k] = s * inv;
            }
            T[i * (i + 1) / 2 + i] = inv;
        }
        if (lane == 0) {
            #pragma unroll
            for (int t = 0; t < NG; t++) Tm[t] = T[t];
        }
    }
    __syncthreads();

    // ---- D: apply b_i = sum_{k<=i} T[i][k] v_k, streaming store ----
    #pragma unroll
    for (int i = 0; i < NV; i++) {
        float4 acc = make_float4(0.0f, 0.0f, 0.0f, 0.0f);
        #pragma unroll
        for (int k = 0; k <= i; k++) {
            float t = Tm[i * (i + 1) / 2 + k];  // LDS broadcast
            acc.x += t * v[k].x;
            acc.y += t * v[k].y;
            acc.z += t * v[k].z;
            acc.w += t * v[k].w;
        }
        __stcs(&xout[(size_t)i * NSTRIDE_F4], acc);
    }
}

extern "C" void kernel_launch(void* const* d_in, const int* in_sizes, int n_in,
                              void* d_out, int out_size) {
    const float* x = (const float*)d_in[0];
    float* out = (float*)d_out;
    gram_schmidt_kernel<<<NPROB, 256>>>(x, out);
}